// round 8
// baseline (speedup 1.0000x reference)
#include <cuda_runtime.h>
#include <cuda_bf16.h>
#include <cstdint>
#include <cstddef>

#define B_   64
#define S_   512
#define E_   300
#define EP_  304
#define M_   32768

__device__ float g_x[M_ * EP_];
__device__ float g_w0pad[2][1024 * EP_];
__device__ float g_gx0[M_ * 2048];
__device__ float g_h1 [M_ * 512];
__device__ float g_gx1[M_ * 2048];
__device__ float g_h2 [M_ * 512];
__device__ float g_err[M_];

#define FMA2(acc, a, b) \
    asm("fma.rn.f32x2 %0, %1, %2, %0;" : "+l"(acc) : "l"(a), "l"(b))
#define PACK2(out, x) \
    asm("mov.b64 %0, {%1, %1};" : "=l"(out) : "f"(x))
#define UNPACK2(lo, hi, v) \
    asm("mov.b64 {%0, %1}, %2;" : "=f"(lo), "=f"(hi) : "l"(v))

__device__ __forceinline__ float sigm(float x) { return 1.0f / (1.0f + expf(-x)); }

__device__ __forceinline__ void mbar_wait_cluster(uint32_t addr, uint32_t parity) {
    asm volatile(
        "{\n\t.reg .pred P;\n\t"
        "WL_%=:\n\t"
        "mbarrier.try_wait.parity.acquire.cluster.shared::cta.b64 P, [%0], %1, 0x989680;\n\t"
        "@!P bra WL_%=;\n\t"
        "}" :: "r"(addr), "r"(parity) : "memory");
}

__global__ void gather_kernel(const int* __restrict__ ids, const float* __restrict__ emb) {
    int m = blockIdx.x, s = m >> 6, b = m & 63;
    int id = ids[b * S_ + s];
    const float* src = emb + (size_t)id * E_;
    float* dst = g_x + (size_t)m * EP_;
    for (int e = threadIdx.x; e < EP_; e += blockDim.x)
        dst[e] = (e < E_) ? src[e] : 0.0f;
}

__global__ void padw_kernel(const float* __restrict__ wf, const float* __restrict__ wb) {
    int row = blockIdx.x & 1023, dir = blockIdx.x >> 10;
    const float* src = (dir ? wb : wf) + (size_t)row * E_;
    float* dst = g_w0pad[dir] + (size_t)row * EP_;
    for (int e = threadIdx.x; e < EP_; e += blockDim.x)
        dst[e] = (e < E_) ? src[e] : 0.0f;
}

// BM=128,BN=64,BK=16, double-buffered, fma.rn.f32x2 inner.
__global__ void sgemm_kernel(int layer, int dir,
                             const float* __restrict__ Wext,
                             const float* __restrict__ b1,
                             const float* __restrict__ b2) {
    const float* A; const float* W; float* C; int lda, K;
    if (layer == 0) { A = g_x;  lda = EP_; K = EP_; W = g_w0pad[dir]; C = g_gx0; }
    else            { A = g_h1; lda = 512; K = 512; W = Wext;         C = g_gx1; }
    const int coloff = dir << 10;

    __shared__ float As[2][16][132];
    __shared__ float Bs[2][16][68];

    const int tid = threadIdx.x;
    const int m0 = blockIdx.y * 128, n0 = blockIdx.x * 64;
    const int tx = tid & 15, ty = tid >> 4;
    const int arow = tid >> 2, acol = (tid & 3) * 4;

    unsigned long long acc2[4][4];
#pragma unroll
    for (int i = 0; i < 4; ++i)
#pragma unroll
        for (int j = 0; j < 4; ++j) acc2[i][j] = 0ULL;

    const int nIter = K >> 4;
    {
        float4 a0 = *(const float4*)(A + (size_t)(m0 + arow)      * lda + acol);
        float4 a1 = *(const float4*)(A + (size_t)(m0 + arow + 64) * lda + acol);
        float4 bv = *(const float4*)(W + (size_t)(n0 + arow)      * lda + acol);
        As[0][acol + 0][arow] = a0.x; As[0][acol + 1][arow] = a0.y;
        As[0][acol + 2][arow] = a0.z; As[0][acol + 3][arow] = a0.w;
        As[0][acol + 0][arow + 64] = a1.x; As[0][acol + 1][arow + 64] = a1.y;
        As[0][acol + 2][arow + 64] = a1.z; As[0][acol + 3][arow + 64] = a1.w;
        Bs[0][acol + 0][arow] = bv.x; Bs[0][acol + 1][arow] = bv.y;
        Bs[0][acol + 2][arow] = bv.z; Bs[0][acol + 3][arow] = bv.w;
    }
    __syncthreads();

    for (int it = 0; it < nIter; ++it) {
        const int cur = it & 1, nxt = cur ^ 1;
        const bool more = (it + 1 < nIter);
        float4 na0, na1, nbv;
        if (more) {
            const int k0 = (it + 1) << 4;
            na0 = *(const float4*)(A + (size_t)(m0 + arow)      * lda + k0 + acol);
            na1 = *(const float4*)(A + (size_t)(m0 + arow + 64) * lda + k0 + acol);
            nbv = *(const float4*)(W + (size_t)(n0 + arow)      * lda + k0 + acol);
        }
#pragma unroll
        for (int k = 0; k < 16; ++k) {
            const float* ar = &As[cur][k][ty * 8];
            ulonglong2 a01 = *(const ulonglong2*)ar;
            ulonglong2 a23 = *(const ulonglong2*)(ar + 4);
            float4 bw = *(const float4*)&Bs[cur][k][tx * 4];
            unsigned long long bd[4];
            PACK2(bd[0], bw.x); PACK2(bd[1], bw.y);
            PACK2(bd[2], bw.z); PACK2(bd[3], bw.w);
#pragma unroll
            for (int j = 0; j < 4; ++j) {
                FMA2(acc2[0][j], a01.x, bd[j]);
                FMA2(acc2[1][j], a01.y, bd[j]);
                FMA2(acc2[2][j], a23.x, bd[j]);
                FMA2(acc2[3][j], a23.y, bd[j]);
            }
        }
        if (more) {
            As[nxt][acol + 0][arow] = na0.x; As[nxt][acol + 1][arow] = na0.y;
            As[nxt][acol + 2][arow] = na0.z; As[nxt][acol + 3][arow] = na0.w;
            As[nxt][acol + 0][arow + 64] = na1.x; As[nxt][acol + 1][arow + 64] = na1.y;
            As[nxt][acol + 2][arow + 64] = na1.z; As[nxt][acol + 3][arow + 64] = na1.w;
            Bs[nxt][acol + 0][arow] = nbv.x; Bs[nxt][acol + 1][arow] = nbv.y;
            Bs[nxt][acol + 2][arow] = nbv.z; Bs[nxt][acol + 3][arow] = nbv.w;
        }
        __syncthreads();
    }

    const int ng = n0 + tx * 4;
    float bsum[4];
#pragma unroll
    for (int j = 0; j < 4; ++j) bsum[j] = b1[ng + j] + b2[ng + j];
#pragma unroll
    for (int p = 0; p < 4; ++p) {
        float lo[4], hi[4];
#pragma unroll
        for (int j = 0; j < 4; ++j) UNPACK2(lo[j], hi[j], acc2[p][j]);
        int m = m0 + ty * 8 + p * 2;
        float4 o0, o1;
        o0.x = lo[0] + bsum[0]; o0.y = lo[1] + bsum[1];
        o0.z = lo[2] + bsum[2]; o0.w = lo[3] + bsum[3];
        o1.x = hi[0] + bsum[0]; o1.y = hi[1] + bsum[1];
        o1.z = hi[2] + bsum[2]; o1.w = hi[3] + bsum[3];
        *(float4*)(C + (size_t)m * 2048 + coloff + ng) = o0;
        *(float4*)(C + (size_t)(m + 1) * 2048 + coloff + ng) = o1;
    }
}

// Cluster bi-LSTM: 128 CTAs, cluster(8). cid: dir=cid>>3, bg=cid&7.
// thread: rg=tid>>3 (dim), bg2=(tid>>2)&1, kid=tid&3 (k-quarter).
// smem floats: Wsl 128*264=33792 @0; Hb 2*2144 @33792; Gxs 2*1088 @38080;
//              mbar 2xu64 @40256; total 40264
#define LSTM_SMEM_FLOATS 40264
#define LSTM_SMEM_BYTES (LSTM_SMEM_FLOATS * 4)

__global__ void __launch_bounds__(256, 1) __cluster_dims__(8, 1, 1)
lstm_kernel(int layer, const float* __restrict__ whh_f,
            const float* __restrict__ whh_b) {
    extern __shared__ float smf[];
    float* Wsl = smf;
    float* Hb  = smf + 33792;
    float* Gxs = smf + 38080;
    uint32_t mb_local = (uint32_t)__cvta_generic_to_shared(smf + 40256);

    const int tid = threadIdx.x;
    uint32_t rank; asm("mov.u32 %0, %%cluster_ctarank;" : "=r"(rank));
    const int cid = blockIdx.x >> 3, dir = cid >> 3, bg = cid & 7;
    const int j0 = (int)(rank << 5);
    const float* whh  = dir ? whh_b : whh_f;
    const float* gx   = layer ? g_gx1 : g_gx0;
    float*       hout = layer ? g_h2  : g_h1;

    {   // W: smem row (q*32+tw)*264 <- whh[q*256 + j0 + tw][:]
        int rloc = tid >> 1, half = (tid & 1) << 7;
        int q = rloc >> 5, tw = rloc & 31;
        const float4* src = (const float4*)(whh + (size_t)((q << 8) + j0 + tw) * 256 + half);
        float4* dst = (float4*)(Wsl + rloc * 264 + half);
#pragma unroll
        for (int i = 0; i < 32; ++i) dst[i] = src[i];
    }
    for (int i = tid; i < 4288; i += 256) Hb[i] = 0.0f;
    const int pb = tid >> 5, pw = tid & 31, pq = pw >> 3, pe = pw & 7;
    {   // Gxs[0] prefill for t=0
        int s0 = dir ? 511 : 0;
        float4 gv = *(const float4*)(gx + (size_t)(s0 * 64 + bg * 8 + pb) * 2048
                                       + (dir << 10) + (pq << 8) + j0 + (pe << 2));
        *(float4*)(Gxs + pb * 136 + (pq << 5) + (pe << 2)) = gv;
    }
    uint32_t hb_peer[8], mb_peer[8];
    {
        uint32_t hb0 = (uint32_t)__cvta_generic_to_shared(Hb);
#pragma unroll
        for (int p = 0; p < 8; ++p) {
            asm("mapa.shared::cluster.u32 %0, %1, %2;" : "=r"(hb_peer[p]) : "r"(hb0), "r"(p));
            asm("mapa.shared::cluster.u32 %0, %1, %2;" : "=r"(mb_peer[p]) : "r"(mb_local), "r"(p));
        }
    }
    if (tid == 0) {
        asm volatile("mbarrier.init.shared.b64 [%0], %1;" :: "r"(mb_local), "r"(64u) : "memory");
        asm volatile("mbarrier.init.shared.b64 [%0], %1;" :: "r"(mb_local + 8), "r"(64u) : "memory");
    }
    asm volatile("barrier.cluster.arrive.aligned;" ::: "memory");
    asm volatile("barrier.cluster.wait.aligned;" ::: "memory");

    const int rg = tid >> 3, bg2 = (tid >> 2) & 1, kid = tid & 3;
    const int bat = (bg2 << 2) + ((kid & 1) << 1) + ((kid >> 1) & 1);
    const float* wb = Wsl + rg * 264 + (kid << 2);
    float creg = 0.0f;
    int par0 = 0, par1 = 0;

    for (int t = 0; t < 512; ++t) {
        const int s = dir ? 511 - t : t;
        const int cur = t & 1, nxt = cur ^ 1;

        float4 gv;   // prefetch gx(t+1)
        {
            int t2 = (t < 511) ? t + 1 : t;
            int s2 = dir ? 511 - t2 : t2;
            gv = *(const float4*)(gx + (size_t)(s2 * 64 + bg * 8 + pb) * 2048
                                    + (dir << 10) + (pq << 8) + j0 + (pe << 2));
        }

        if (t > 0) {
            uint32_t mb = mb_local + ((uint32_t)cur << 3);
            if (cur) { mbar_wait_cluster(mb, (uint32_t)par1); par1 ^= 1; }
            else     { mbar_wait_cluster(mb, (uint32_t)par0); par0 ^= 1; }
        }

        // dot: 4 gates x 4 bats, k in [kid*4 + c*16, +4) over c=0..15
        unsigned long long acc2[4][4];
#pragma unroll
        for (int q = 0; q < 4; ++q)
#pragma unroll
            for (int j = 0; j < 4; ++j) acc2[q][j] = 0ULL;

        const float* hbb = Hb + cur * 2144 + bg2 * 1072 + (kid << 2);
#pragma unroll 4
        for (int c = 0; c < 16; ++c) {
            const float* wc = wb + c * 16;
            const float* hc = hbb + c * 16;
            ulonglong2 w0 = *(const ulonglong2*)(wc);
            ulonglong2 w1 = *(const ulonglong2*)(wc + 8448);
            ulonglong2 w2 = *(const ulonglong2*)(wc + 16896);
            ulonglong2 w3 = *(const ulonglong2*)(wc + 25344);
            ulonglong2 h0 = *(const ulonglong2*)(hc);
            ulonglong2 h1v = *(const ulonglong2*)(hc + 268);
            ulonglong2 h2v = *(const ulonglong2*)(hc + 536);
            ulonglong2 h3v = *(const ulonglong2*)(hc + 804);
            FMA2(acc2[0][0], w0.x, h0.x);  FMA2(acc2[0][0], w0.y, h0.y);
            FMA2(acc2[0][1], w0.x, h1v.x); FMA2(acc2[0][1], w0.y, h1v.y);
            FMA2(acc2[0][2], w0.x, h2v.x); FMA2(acc2[0][2], w0.y, h2v.y);
            FMA2(acc2[0][3], w0.x, h3v.x); FMA2(acc2[0][3], w0.y, h3v.y);
            FMA2(acc2[1][0], w1.x, h0.x);  FMA2(acc2[1][0], w1.y, h0.y);
            FMA2(acc2[1][1], w1.x, h1v.x); FMA2(acc2[1][1], w1.y, h1v.y);
            FMA2(acc2[1][2], w1.x, h2v.x); FMA2(acc2[1][2], w1.y, h2v.y);
            FMA2(acc2[1][3], w1.x, h3v.x); FMA2(acc2[1][3], w1.y, h3v.y);
            FMA2(acc2[2][0], w2.x, h0.x);  FMA2(acc2[2][0], w2.y, h0.y);
            FMA2(acc2[2][1], w2.x, h1v.x); FMA2(acc2[2][1], w2.y, h1v.y);
            FMA2(acc2[2][2], w2.x, h2v.x); FMA2(acc2[2][2], w2.y, h2v.y);
            FMA2(acc2[2][3], w2.x, h3v.x); FMA2(acc2[2][3], w2.y, h3v.y);
            FMA2(acc2[3][0], w3.x, h0.x);  FMA2(acc2[3][0], w3.y, h0.y);
            FMA2(acc2[3][1], w3.x, h1v.x); FMA2(acc2[3][1], w3.y, h1v.y);
            FMA2(acc2[3][2], w3.x, h2v.x); FMA2(acc2[3][2], w3.y, h2v.y);
            FMA2(acc2[3][3], w3.x, h3v.x); FMA2(acc2[3][3], w3.y, h3v.y);
        }

        // reduce-scatter over kid lanes: lane ends with 4 gate sums of its bat
        float g4[4];
#pragma unroll
        for (int q = 0; q < 4; ++q) {
            float v0, v1, v2, v3, hx;
            UNPACK2(v0, hx, acc2[q][0]); v0 += hx;
            UNPACK2(v1, hx, acc2[q][1]); v1 += hx;
            UNPACK2(v2, hx, acc2[q][2]); v2 += hx;
            UNPACK2(v3, hx, acc2[q][3]); v3 += hx;
            float y0 = __shfl_xor_sync(0xffffffffu, v0, 1);
            float y1 = __shfl_xor_sync(0xffffffffu, v1, 1);
            float y2 = __shfl_xor_sync(0xffffffffu, v2, 1);
            float y3 = __shfl_xor_sync(0xffffffffu, v3, 1);
            float u0 = (kid & 1) ? (v2 + y2) : (v0 + y0);
            float u1 = (kid & 1) ? (v3 + y3) : (v1 + y1);
            float z0 = __shfl_xor_sync(0xffffffffu, u0, 2);
            float z1 = __shfl_xor_sync(0xffffffffu, u1, 2);
            g4[q] = (kid & 2) ? (u1 + z1) : (u0 + z0);
        }

        // gate update for (dim j0+rg, bat)
        const float* gxb = Gxs + cur * 1088 + bat * 136;
        float gi = g4[0] + gxb[rg];
        float gf = g4[1] + gxb[32 + rg];
        float gg = g4[2] + gxb[64 + rg];
        float go = g4[3] + gxb[96 + rg];
        float c = sigm(gf) * creg + sigm(gi) * tanhf(gg);
        creg = c;
        float h = sigm(go) * tanhf(c);

        // stage gx(t+1)
        *(float4*)(Gxs + nxt * 1088 + pb * 136 + (pq << 5) + (pe << 2)) = gv;

        // publish h(t+1) to all cluster CTAs, then per-warp release-arrive
        float h1 = __shfl_down_sync(0xffffffffu, h, 8);
        float h2 = __shfl_down_sync(0xffffffffu, h, 16);
        float h3 = __shfl_down_sync(0xffffffffu, h, 24);
        if (t < 511) {
            if ((tid & 24) == 0) {
                uint32_t off = (uint32_t)((nxt * 2144 + bat * 268 + j0 + ((tid >> 5) << 2)) << 2);
#pragma unroll
                for (int p = 0; p < 8; ++p)
                    asm volatile("st.shared::cluster.v4.f32 [%0], {%1,%2,%3,%4};"
                                 :: "r"(hb_peer[p] + off), "f"(h), "f"(h1), "f"(h2), "f"(h3)
                                 : "memory");
            }
            __syncwarp();
            if ((tid & 31) == 0) {
                asm volatile("fence.acq_rel.cluster;" ::: "memory");
#pragma unroll
                for (int p = 0; p < 8; ++p)
                    asm volatile("mbarrier.arrive.release.cluster.shared::cluster.b64 _, [%0];"
                                 :: "r"(mb_peer[p] + ((uint32_t)nxt << 3)) : "memory");
            }
        }
        hout[(size_t)(s * 64 + bg * 8 + bat) * 512 + (dir << 8) + j0 + rg] = h;
    }
}

__global__ void score_kernel(const float* __restrict__ wlin,
                             const float* __restrict__ blin,
                             const float* __restrict__ labels,
                             const int* __restrict__ masks,
                             float* __restrict__ outs) {
    int w = blockIdx.x * 8 + (threadIdx.x >> 5);
    int lane = threadIdx.x & 31;
    int s = w >> 6, b = w & 63;
    const float* hp = g_h2 + (size_t)w * 512;
    float acc = 0.0f;
#pragma unroll
    for (int j = lane; j < 256; j += 32)
        acc += 0.5f * (hp[j] + hp[256 + j]) * wlin[j];
#pragma unroll
    for (int d = 16; d; d >>= 1) acc += __shfl_xor_sync(0xffffffffu, acc, d);
    if (lane == 0) {
        float sc = sigm(acc + blin[0]);
        int oi = b * S_ + s;
        outs[oi] = sc;
        float df = sc - labels[oi];
        g_err[oi] = df * df * (float)masks[oi];
    }
}

__global__ void loss_kernel(const int* __restrict__ masks,
                            float* __restrict__ out, int out_size) {
    __shared__ float sr[64];
    int b = threadIdx.x;
    if (b < 64) {
        float se = 0.0f, sm = 0.0f;
        for (int s = 0; s < S_; ++s) {
            se += g_err[b * S_ + s];
            sm += (float)masks[b * S_ + s];
        }
        sr[b] = se / sm;
    }
    __syncthreads();
    if (threadIdx.x == 0 && out_size > M_) {
        float t = 0.0f;
        for (int i = 0; i < 64; ++i) t += sr[i];
        out[M_] = t / 64.0f;
    }
}

extern "C" void kernel_launch(void* const* d_in, const int* in_sizes, int n_in,
                              void* d_out, int out_size) {
    const int*   ids    = (const int*)d_in[0];
    const float* labels = (const float*)d_in[1];
    const int*   masks  = (const int*)d_in[2];
    const float* emb    = (const float*)d_in[3];
    const float* wih0f = (const float*)d_in[4];
    const float* whh0f = (const float*)d_in[5];
    const float* bih0f = (const float*)d_in[6];
    const float* bhh0f = (const float*)d_in[7];
    const float* wih0b = (const float*)d_in[8];
    const float* whh0b = (const float*)d_in[9];
    const float* bih0b = (const float*)d_in[10];
    const float* bhh0b = (const float*)d_in[11];
    const float* wih1f = (const float*)d_in[12];
    const float* whh1f = (const float*)d_in[13];
    const float* bih1f = (const float*)d_in[14];
    const float* bhh1f = (const float*)d_in[15];
    const float* wih1b = (const float*)d_in[16];
    const float* whh1b = (const float*)d_in[17];
    const float* bih1b = (const float*)d_in[18];
    const float* bhh1b = (const float*)d_in[19];
    const float* wlin  = (const float*)d_in[20];
    const float* blin  = (const float*)d_in[21];
    float* out = (float*)d_out;

    static bool attr_done = false;
    if (!attr_done) {
        cudaFuncSetAttribute(lstm_kernel, cudaFuncAttributeMaxDynamicSharedMemorySize,
                             LSTM_SMEM_BYTES);
        attr_done = true;
    }

    gather_kernel<<<M_, 128>>>(ids, emb);
    padw_kernel<<<2048, 128>>>(wih0f, wih0b);

    dim3 gg(16, 256);
    sgemm_kernel<<<gg, 256>>>(0, 0, nullptr, bih0f, bhh0f);
    sgemm_kernel<<<gg, 256>>>(0, 1, nullptr, bih0b, bhh0b);

    lstm_kernel<<<128, 256, LSTM_SMEM_BYTES>>>(0, whh0f, whh0b);

    sgemm_kernel<<<gg, 256>>>(1, 0, wih1f, bih1f, bhh1f);
    sgemm_kernel<<<gg, 256>>>(1, 1, wih1b, bih1b, bhh1b);

    lstm_kernel<<<128, 256, LSTM_SMEM_BYTES>>>(1, whh1f, whh1b);

    score_kernel<<<M_ / 8, 256>>>(wlin, blin, labels, masks, out);
    loss_kernel<<<1, 64>>>(masks, out, out_size);
}

// round 10
// speedup vs baseline: 1.5015x; 1.5015x over previous
#include <cuda_runtime.h>
#include <cuda_bf16.h>
#include <cstdint>
#include <cstddef>

#define B_   64
#define S_   512
#define E_   300
#define EP_  304
#define M_   32768

__device__ float g_x[M_ * EP_];
__device__ float g_w0pad[2][1024 * EP_];
__device__ float g_gx0[M_ * 2048];
__device__ float g_h1 [M_ * 512];
__device__ float g_gx1[M_ * 2048];
__device__ float g_h2 [M_ * 512];
__device__ float g_hbuf[2][2][B_ * 256];
__device__ float g_err[M_];
__device__ unsigned g_c1[8 * 32];     // group counters, 128B apart
__device__ unsigned g_croot[32];

#define FMA2(acc, a, b) \
    asm("fma.rn.f32x2 %0, %1, %2, %0;" : "+l"(acc) : "l"(a), "l"(b))
#define PACK2(out, x) \
    asm("mov.b64 %0, {%1, %1};" : "=l"(out) : "f"(x))
#define UNPACK2(lo, hi, v) \
    asm("mov.b64 {%0, %1}, %2;" : "=f"(lo), "=f"(hi) : "l"(v))

__device__ __forceinline__ float sigm(float x) { return 1.0f / (1.0f + expf(-x)); }

// e^{-ax} for ax >= 0, FMA/ALU only (no MUFU). err ~1.2e-7 rel.
__device__ __forceinline__ float exp_neg(float ax) {
    float t = fmaxf(-ax * 1.44269504088896f, -80.0f);
    float r = t + 12582912.0f;                       // round-to-nearest int
    int   n = __float_as_int(r) - 0x4B400000;
    float f = t - (r - 12582912.0f);                 // f in [-0.5, 0.5]
    float y = f * 0.693147180559945f;
    float p = 1.3888889e-3f;
    p = fmaf(p, y, 8.3333333e-3f);
    p = fmaf(p, y, 4.1666667e-2f);
    p = fmaf(p, y, 1.6666667e-1f);
    p = fmaf(p, y, 0.5f);
    p = fmaf(p, y, 1.0f);
    p = fmaf(p, y, 1.0f);
    return __int_as_float(__float_as_int(p) + (n << 23));
}
// 1/d for d in [1,2], FMA-only Newton. err ~3e-9.
__device__ __forceinline__ float recip12(float d) {
    float r = fmaf(-0.45710678f, d, 1.45710678f);
    r = fmaf(r, fmaf(-d, r, 1.0f), r);
    r = fmaf(r, fmaf(-d, r, 1.0f), r);
    r = fmaf(r, fmaf(-d, r, 1.0f), r);
    return r;
}
__device__ __forceinline__ float sigm_f(float x) {
    float u = exp_neg(fabsf(x));
    float r = recip12(1.0f + u);
    return x >= 0.0f ? r : u * r;
}
__device__ __forceinline__ float tanh_f(float x) {
    float u = exp_neg(2.0f * fabsf(x));
    float m = (1.0f - u) * recip12(1.0f + u);
    return x >= 0.0f ? m : -m;
}

__global__ void zerocnt_kernel() {
    int i = threadIdx.x;
    if (i < 8 * 32) g_c1[i] = 0u;
    if (i == 0) g_croot[0] = 0u;
}

__global__ void gather_kernel(const int* __restrict__ ids, const float* __restrict__ emb) {
    int m = blockIdx.x, s = m >> 6, b = m & 63;
    int id = ids[b * S_ + s];
    const float* src = emb + (size_t)id * E_;
    float* dst = g_x + (size_t)m * EP_;
    for (int e = threadIdx.x; e < EP_; e += blockDim.x)
        dst[e] = (e < E_) ? src[e] : 0.0f;
}

__global__ void padw_kernel(const float* __restrict__ wf, const float* __restrict__ wb) {
    int row = blockIdx.x & 1023, dir = blockIdx.x >> 10;
    const float* src = (dir ? wb : wf) + (size_t)row * E_;
    float* dst = g_w0pad[dir] + (size_t)row * EP_;
    for (int e = threadIdx.x; e < EP_; e += blockDim.x)
        dst[e] = (e < E_) ? src[e] : 0.0f;
}

// BM=128,BN=64,BK=16, double-buffered, fma.rn.f32x2 inner.
__global__ void sgemm_kernel(int layer, int dir,
                             const float* __restrict__ Wext,
                             const float* __restrict__ b1,
                             const float* __restrict__ b2) {
    const float* A; const float* W; float* C; int lda, K;
    if (layer == 0) { A = g_x;  lda = EP_; K = EP_; W = g_w0pad[dir]; C = g_gx0; }
    else            { A = g_h1; lda = 512; K = 512; W = Wext;         C = g_gx1; }
    const int coloff = dir << 10;

    __shared__ float As[2][16][132];
    __shared__ float Bs[2][16][68];

    const int tid = threadIdx.x;
    const int m0 = blockIdx.y * 128, n0 = blockIdx.x * 64;
    const int tx = tid & 15, ty = tid >> 4;
    const int arow = tid >> 2, acol = (tid & 3) * 4;

    unsigned long long acc2[4][4];
#pragma unroll
    for (int i = 0; i < 4; ++i)
#pragma unroll
        for (int j = 0; j < 4; ++j) acc2[i][j] = 0ULL;

    const int nIter = K >> 4;
    {
        float4 a0 = *(const float4*)(A + (size_t)(m0 + arow)      * lda + acol);
        float4 a1 = *(const float4*)(A + (size_t)(m0 + arow + 64) * lda + acol);
        float4 bv = *(const float4*)(W + (size_t)(n0 + arow)      * lda + acol);
        As[0][acol + 0][arow] = a0.x; As[0][acol + 1][arow] = a0.y;
        As[0][acol + 2][arow] = a0.z; As[0][acol + 3][arow] = a0.w;
        As[0][acol + 0][arow + 64] = a1.x; As[0][acol + 1][arow + 64] = a1.y;
        As[0][acol + 2][arow + 64] = a1.z; As[0][acol + 3][arow + 64] = a1.w;
        Bs[0][acol + 0][arow] = bv.x; Bs[0][acol + 1][arow] = bv.y;
        Bs[0][acol + 2][arow] = bv.z; Bs[0][acol + 3][arow] = bv.w;
    }
    __syncthreads();

    for (int it = 0; it < nIter; ++it) {
        const int cur = it & 1, nxt = cur ^ 1;
        const bool more = (it + 1 < nIter);
        float4 na0, na1, nbv;
        if (more) {
            const int k0 = (it + 1) << 4;
            na0 = *(const float4*)(A + (size_t)(m0 + arow)      * lda + k0 + acol);
            na1 = *(const float4*)(A + (size_t)(m0 + arow + 64) * lda + k0 + acol);
            nbv = *(const float4*)(W + (size_t)(n0 + arow)      * lda + k0 + acol);
        }
#pragma unroll
        for (int k = 0; k < 16; ++k) {
            const float* ar = &As[cur][k][ty * 8];
            ulonglong2 a01 = *(const ulonglong2*)ar;
            ulonglong2 a23 = *(const ulonglong2*)(ar + 4);
            float4 bw = *(const float4*)&Bs[cur][k][tx * 4];
            unsigned long long bd[4];
            PACK2(bd[0], bw.x); PACK2(bd[1], bw.y);
            PACK2(bd[2], bw.z); PACK2(bd[3], bw.w);
#pragma unroll
            for (int j = 0; j < 4; ++j) {
                FMA2(acc2[0][j], a01.x, bd[j]);
                FMA2(acc2[1][j], a01.y, bd[j]);
                FMA2(acc2[2][j], a23.x, bd[j]);
                FMA2(acc2[3][j], a23.y, bd[j]);
            }
        }
        if (more) {
            As[nxt][acol + 0][arow] = na0.x; As[nxt][acol + 1][arow] = na0.y;
            As[nxt][acol + 2][arow] = na0.z; As[nxt][acol + 3][arow] = na0.w;
            As[nxt][acol + 0][arow + 64] = na1.x; As[nxt][acol + 1][arow + 64] = na1.y;
            As[nxt][acol + 2][arow + 64] = na1.z; As[nxt][acol + 3][arow + 64] = na1.w;
            Bs[nxt][acol + 0][arow] = nbv.x; Bs[nxt][acol + 1][arow] = nbv.y;
            Bs[nxt][acol + 2][arow] = nbv.z; Bs[nxt][acol + 3][arow] = nbv.w;
        }
        __syncthreads();
    }

    const int ng = n0 + tx * 4;
    float bsum[4];
#pragma unroll
    for (int j = 0; j < 4; ++j) bsum[j] = b1[ng + j] + b2[ng + j];
#pragma unroll
    for (int p = 0; p < 4; ++p) {
        float lo[4], hi[4];
#pragma unroll
        for (int j = 0; j < 4; ++j) UNPACK2(lo[j], hi[j], acc2[p][j]);
        int m = m0 + ty * 8 + p * 2;
        float4 o0, o1;
        o0.x = lo[0] + bsum[0]; o0.y = lo[1] + bsum[1];
        o0.z = lo[2] + bsum[2]; o0.w = lo[3] + bsum[3];
        o1.x = hi[0] + bsum[0]; o1.y = hi[1] + bsum[1];
        o1.z = hi[2] + bsum[2]; o1.w = hi[3] + bsum[3];
        *(float4*)(C + (size_t)m * 2048 + coloff + ng) = o0;
        *(float4*)(C + (size_t)(m + 1) * 2048 + coloff + ng) = o1;
    }
}

// Hierarchical grid barrier: 8 groups of 16 CTAs + root. Monotonic index k.
__device__ __forceinline__ void gbar(int tid, unsigned grp, unsigned k) {
    __threadfence();
    __syncthreads();
    if (tid == 0) {
        unsigned a = atomicAdd(&g_c1[grp * 32], 1u) + 1u;
        if (a == 16u * k) atomicAdd(&g_croot[0], 1u);
        while (*(volatile unsigned*)&g_croot[0] < 8u * k) { }
        __threadfence();
    }
    __syncthreads();
}

// Persistent bi-LSTM: grid 128, 256 thr. CTA = (dir, 4 h-dims).
// smem: Ws[16][264] @0, Hs[64][264] @4224, Gxs[2][64][20] @21120, Gs[64][20] @23680
#define LSTM_SMEM_FLOATS 24960
#define LSTM_SMEM_BYTES (LSTM_SMEM_FLOATS * 4)

__global__ void __launch_bounds__(256, 1)
lstm_kernel(int layer, const float* __restrict__ whh_f,
            const float* __restrict__ whh_b) {
    extern __shared__ float smf[];
    float* Ws  = smf;
    float* Hs  = smf + 4224;
    float* Gxs = smf + 21120;
    float* Gs  = smf + 23680;

    const int tid = threadIdx.x;
    const int dir = blockIdx.x >> 6;
    const int j0  = (blockIdx.x & 63) << 2;
    const unsigned grp = (unsigned)blockIdx.x >> 4;
    const float* whh  = dir ? whh_b : whh_f;
    const float* gx   = layer ? g_gx1 : g_gx0;
    float*       hout = layer ? g_h2  : g_h1;
    float* hb0 = &g_hbuf[0][dir][0];
    float* hb1 = &g_hbuf[1][dir][0];

    {   // W: smem row lr=q*4+jj (stride 264) <- whh[q*256 + j0 + jj][:]
        int lr = tid >> 4, seg = tid & 15;
        int q = lr >> 2, jj = lr & 3;
        const float4* src = (const float4*)(whh + (size_t)((q << 8) + j0 + jj) * 256 + seg * 16);
        float4* dst = (float4*)(Ws + lr * 264 + seg * 16);
        dst[0] = src[0]; dst[1] = src[1]; dst[2] = src[2]; dst[3] = src[3];
    }
    const int ujj = tid >> 6, ubat = tid & 63;   // update cell
    hb0[ubat * 256 + j0 + ujj] = 0.0f;           // h(0)=0 for own dims
    const int pb = tid >> 2, pq = tid & 3;       // gx prefetch ids
    {
        int s0 = dir ? 511 : 0;
        float4 gv = *(const float4*)(gx + (size_t)(s0 * 64 + pb) * 2048
                                       + (dir << 10) + (pq << 8) + j0);
        *(float4*)(Gxs + pb * 20 + pq * 4) = gv;
    }
    unsigned kbar = 1u;
    gbar(tid, grp, kbar);

    const int kid = tid & 7;
    const int a8  = (tid >> 3) & 3;   // gate group
    const int w   = tid >> 5;         // warp -> bats w*8..w*8+7
    const float* wsl = Ws + (a8 << 2) * 264 + (kid << 2);
    float creg = 0.0f;

    for (int t = 0; t < 512; ++t) {
        const int s = dir ? 511 - t : t;
        const int cur = t & 1, nxt = cur ^ 1;
        const float* hsrc = cur ? hb1 : hb0;
        float*       hdst = cur ? hb0 : hb1;

        {   // stage h(t) into Hs[bat][264]
            const float4* hg = (const float4*)hsrc;
#pragma unroll
            for (int i = 0; i < 16; ++i) {
                int idx = (i << 8) + tid;
                float4 v = __ldcg(hg + idx);
                int bat = idx >> 6, d4 = idx & 63;
                *(float4*)(Hs + bat * 264 + (d4 << 2)) = v;
            }
        }
        float4 gv;   // prefetch gx(t+1)
        {
            int t2 = (t < 511) ? t + 1 : t;
            int s2 = dir ? 511 - t2 : t2;
            gv = *(const float4*)(gx + (size_t)(s2 * 64 + pb) * 2048
                                    + (dir << 10) + (pq << 8) + j0);
        }
        __syncthreads();

        // dot: gate a8, rows jj=0..3, bats w*8+0..7, k = 4kid+32c
        unsigned long long acc[4][8];
#pragma unroll
        for (int i = 0; i < 4; ++i)
#pragma unroll
            for (int j = 0; j < 8; ++j) acc[i][j] = 0ULL;

        const float* hrow = Hs + (w << 3) * 264 + (kid << 2);
#pragma unroll
        for (int c = 0; c < 8; ++c) {
            const int ko = c << 5;
            ulonglong2 w0 = *(const ulonglong2*)(wsl + ko);
            ulonglong2 w1 = *(const ulonglong2*)(wsl + 264 + ko);
            ulonglong2 w2 = *(const ulonglong2*)(wsl + 528 + ko);
            ulonglong2 w3 = *(const ulonglong2*)(wsl + 792 + ko);
#pragma unroll
            for (int j = 0; j < 8; ++j) {
                ulonglong2 hv = *(const ulonglong2*)(hrow + j * 264 + ko);
                FMA2(acc[0][j], w0.x, hv.x); FMA2(acc[0][j], w0.y, hv.y);
                FMA2(acc[1][j], w1.x, hv.x); FMA2(acc[1][j], w1.y, hv.y);
                FMA2(acc[2][j], w2.x, hv.x); FMA2(acc[2][j], w2.y, hv.y);
                FMA2(acc[3][j], w3.x, hv.x); FMA2(acc[3][j], w3.y, hv.y);
            }
        }

        // reduce-scatter over kid: lane ends with (4 jj) sums for bat=w*8+kid
        float g4[4];
#pragma unroll
        for (int i = 0; i < 4; ++i) {
            float v[8];
#pragma unroll
            for (int j = 0; j < 8; ++j) {
                float lo, hi; UNPACK2(lo, hi, acc[i][j]); v[j] = lo + hi;
            }
            float y0 = __shfl_xor_sync(0xffffffffu, v[0], 4);
            float y1 = __shfl_xor_sync(0xffffffffu, v[1], 4);
            float y2 = __shfl_xor_sync(0xffffffffu, v[2], 4);
            float y3 = __shfl_xor_sync(0xffffffffu, v[3], 4);
            float y4 = __shfl_xor_sync(0xffffffffu, v[4], 4);
            float y5 = __shfl_xor_sync(0xffffffffu, v[5], 4);
            float y6 = __shfl_xor_sync(0xffffffffu, v[6], 4);
            float y7 = __shfl_xor_sync(0xffffffffu, v[7], 4);
            bool b4 = (kid & 4) != 0;
            float u0 = b4 ? v[4] + y4 : v[0] + y0;
            float u1 = b4 ? v[5] + y5 : v[1] + y1;
            float u2 = b4 ? v[6] + y6 : v[2] + y2;
            float u3 = b4 ? v[7] + y7 : v[3] + y3;
            float z0 = __shfl_xor_sync(0xffffffffu, u0, 2);
            float z1 = __shfl_xor_sync(0xffffffffu, u1, 2);
            float z2 = __shfl_xor_sync(0xffffffffu, u2, 2);
            float z3 = __shfl_xor_sync(0xffffffffu, u3, 2);
            bool b2 = (kid & 2) != 0;
            float t0 = b2 ? u2 + z2 : u0 + z0;
            float t1 = b2 ? u3 + z3 : u1 + z1;
            float q0 = __shfl_xor_sync(0xffffffffu, t0, 1);
            float q1 = __shfl_xor_sync(0xffffffffu, t1, 1);
            g4[i] = (kid & 1) ? t1 + q1 : t0 + q0;
        }
        {
            float4 o; o.x = g4[0]; o.y = g4[1]; o.z = g4[2]; o.w = g4[3];
            *(float4*)(Gs + ((w << 3) + kid) * 20 + (a8 << 2)) = o;
        }
        *(float4*)(Gxs + nxt * 1280 + pb * 20 + pq * 4) = gv;
        __syncthreads();

        // update cell (dim j0+ujj, bat ubat) — FMA-only transcendentals
        {
            const float* gsb = Gs + ubat * 20;
            const float* gxb = Gxs + cur * 1280 + ubat * 20;
            float gi = gsb[ujj]      + gxb[ujj];
            float gf = gsb[4 + ujj]  + gxb[4 + ujj];
            float gg = gsb[8 + ujj]  + gxb[8 + ujj];
            float go = gsb[12 + ujj] + gxb[12 + ujj];
            float c = sigm_f(gf) * creg + sigm_f(gi) * tanh_f(gg);
            creg = c;
            float h = sigm_f(go) * tanh_f(c);
            hout[(size_t)(s * 64 + ubat) * 512 + (dir << 8) + j0 + ujj] = h;
            if (t < 511) hdst[ubat * 256 + j0 + ujj] = h;
        }
        if (t < 511) { ++kbar; gbar(tid, grp, kbar); }
    }
}

__global__ void score_kernel(const float* __restrict__ wlin,
                             const float* __restrict__ blin,
                             const float* __restrict__ labels,
                             const int* __restrict__ masks,
                             float* __restrict__ outs) {
    int w = blockIdx.x * 8 + (threadIdx.x >> 5);
    int lane = threadIdx.x & 31;
    int s = w >> 6, b = w & 63;
    const float* hp = g_h2 + (size_t)w * 512;
    float acc = 0.0f;
#pragma unroll
    for (int j = lane; j < 256; j += 32)
        acc += 0.5f * (hp[j] + hp[256 + j]) * wlin[j];
#pragma unroll
    for (int d = 16; d; d >>= 1) acc += __shfl_xor_sync(0xffffffffu, acc, d);
    if (lane == 0) {
        float sc = sigm(acc + blin[0]);
        int oi = b * S_ + s;
        outs[oi] = sc;
        float df = sc - labels[oi];
        g_err[oi] = df * df * (float)masks[oi];
    }
}

__global__ void loss_kernel(const int* __restrict__ masks,
                            float* __restrict__ out, int out_size) {
    __shared__ float sr[64];
    int b = threadIdx.x;
    if (b < 64) {
        float se = 0.0f, sm = 0.0f;
        for (int s = 0; s < S_; ++s) {
            se += g_err[b * S_ + s];
            sm += (float)masks[b * S_ + s];
        }
        sr[b] = se / sm;
    }
    __syncthreads();
    if (threadIdx.x == 0 && out_size > M_) {
        float t = 0.0f;
        for (int i = 0; i < 64; ++i) t += sr[i];
        out[M_] = t / 64.0f;
    }
}

extern "C" void kernel_launch(void* const* d_in, const int* in_sizes, int n_in,
                              void* d_out, int out_size) {
    const int*   ids    = (const int*)d_in[0];
    const float* labels = (const float*)d_in[1];
    const int*   masks  = (const int*)d_in[2];
    const float* emb    = (const float*)d_in[3];
    const float* wih0f = (const float*)d_in[4];
    const float* whh0f = (const float*)d_in[5];
    const float* bih0f = (const float*)d_in[6];
    const float* bhh0f = (const float*)d_in[7];
    const float* wih0b = (const float*)d_in[8];
    const float* whh0b = (const float*)d_in[9];
    const float* bih0b = (const float*)d_in[10];
    const float* bhh0b = (const float*)d_in[11];
    const float* wih1f = (const float*)d_in[12];
    const float* whh1f = (const float*)d_in[13];
    const float* bih1f = (const float*)d_in[14];
    const float* bhh1f = (const float*)d_in[15];
    const float* wih1b = (const float*)d_in[16];
    const float* whh1b = (const float*)d_in[17];
    const float* bih1b = (const float*)d_in[18];
    const float* bhh1b = (const float*)d_in[19];
    const float* wlin  = (const float*)d_in[20];
    const float* blin  = (const float*)d_in[21];
    float* out = (float*)d_out;

    static bool attr_done = false;
    if (!attr_done) {
        cudaFuncSetAttribute(lstm_kernel, cudaFuncAttributeMaxDynamicSharedMemorySize,
                             LSTM_SMEM_BYTES);
        attr_done = true;
    }

    gather_kernel<<<M_, 128>>>(ids, emb);                 // 0
    padw_kernel<<<2048, 128>>>(wih0f, wih0b);             // 1

    dim3 gg(16, 256);
    sgemm_kernel<<<gg, 256>>>(0, 0, nullptr, bih0f, bhh0f);   // 2
    sgemm_kernel<<<gg, 256>>>(0, 1, nullptr, bih0b, bhh0b);   // 3

    zerocnt_kernel<<<1, 256>>>();                         // 4
    lstm_kernel<<<128, 256, LSTM_SMEM_BYTES>>>(0, whh0f, whh0b);  // 5 (ncu slot)

    sgemm_kernel<<<gg, 256>>>(1, 0, wih1f, bih1f, bhh1f); // 6
    sgemm_kernel<<<gg, 256>>>(1, 1, wih1b, bih1b, bhh1b); // 7

    zerocnt_kernel<<<1, 256>>>();                         // 8
    lstm_kernel<<<128, 256, LSTM_SMEM_BYTES>>>(1, whh1f, whh1b);  // 9

    score_kernel<<<M_ / 8, 256>>>(wlin, blin, labels, masks, out);  // 10
    loss_kernel<<<1, 64>>>(masks, out, out_size);                   // 11
}